// round 16
// baseline (speedup 1.0000x reference)
#include <cuda_runtime.h>
#include <math.h>

#define NN 20000
#define NE 50000
#define HH 128
#define UCNT 256
#define MAXDEG 512
#define DSCALE 0.17677669529663687f   // 1/sqrt(32)
#define NTHR 256
#define SMEM_SZ 102400                // 64KB weights + 4KB rows + 32KB partials

// ---------------- device scratch (static, no allocation) ----------------
__device__ int   g_n2s[NN];          // slot+1; 0 = none
__device__ unsigned char g_nneed[NN];
__device__ int   g_deg[UCNT];
__device__ int   g_eidx[UCNT * MAXDEG];
__device__ int   g_nbr[UCNT * MAXDEG];
__device__ int   g_Lcnt;
__device__ int   g_Llist[NN], g_nodeL[NN];
__device__ int   g_tgtL[UCNT], g_canon[UCNT];
__device__ int   g_rowSlot[NN];      // slot+1; 0 = none

__device__ int   g_poff[UCNT + 1];
__device__ int   g_Ptot;
__device__ int   g_pSlot[UCNT * MAXDEG];
__device__ float g_pT[UCNT * MAXDEG];
__device__ int   g_pNbrRow[UCNT * MAXDEG];

__device__ float g_xL[NN * HH];
__device__ float g_tfL[NN * HH];
__device__ float g_q[UCNT * HH];
__device__ float g_agg[UCNT * HH];
__device__ float g_Ak[NN * HH];
__device__ float g_Av[NN * HH];

// base weights (19 transposed) + 6 combined matrices
#define MK0 294912
#define MV0 311296
#define MK1 327680
#define MV1 344064
#define CW0 360448
#define CW1 376832
#define WT_TOTAL 393216
__device__ float g_Wt[WT_TOTAL];
__device__ float g_bvp[2 * HH];      // Wv@b2 + bv
__device__ float g_cb[2 * HH];       // Wop@aoB + opB

__constant__ int c_moutD[19] = {128,128,128,128,128,128,128,128,128,
                                128,128,128,128,128,128,128, 64,128, 64};
__constant__ int c_moff[19]  = {0,16384,32768,49152,65536,81920,98304,114688,
                                131072,147456,163840,180224,196608,212992,
                                229376,245760,262144,270336,286720};

// ---------------- device-wide barrier ----------------
__device__ unsigned g_cnt8[8];
__device__ unsigned g_rootc;
__device__ volatile unsigned g_ep;

__device__ __forceinline__ void gridsync() {
    __syncthreads();
    if (threadIdx.x == 0) {
        unsigned nb = gridDim.x;
        unsigned e = g_ep;
        __threadfence();
        unsigned g = blockIdx.x & 7u;
        unsigned sz = nb / 8u + ((g < (nb & 7u)) ? 1u : 0u);
        if (atomicAdd(&g_cnt8[g], 1u) == sz - 1u) {
            g_cnt8[g] = 0u;
            __threadfence();
            if (atomicAdd(&g_rootc, 1u) == 7u) {
                g_rootc = 0u;
                __threadfence();
                g_ep = e + 1u;
            }
        }
        while (g_ep == e) { }
        __threadfence();
    }
    __syncthreads();
}

// ---------------- helpers ----------------
__device__ __forceinline__ float4 relu4(float4 v) {
    v.x = fmaxf(v.x, 0.f); v.y = fmaxf(v.y, 0.f);
    v.z = fmaxf(v.z, 0.f); v.w = fmaxf(v.w, 0.f);
    return v;
}

__device__ __forceinline__ float matvec64(const float* __restrict__ v,
                                          const float* __restrict__ Wt,
                                          int d, int stride) {
    float a0 = 0.f, a1 = 0.f, a2 = 0.f, a3 = 0.f;
#pragma unroll 8
    for (int k = 0; k < 64; k += 4) {
        a0 = fmaf(v[k],     Wt[(k)     * stride + d], a0);
        a1 = fmaf(v[k + 1], Wt[(k + 1) * stride + d], a1);
        a2 = fmaf(v[k + 2], Wt[(k + 2) * stride + d], a2);
        a3 = fmaf(v[k + 3], Wt[(k + 3) * stride + d], a3);
    }
    return (a0 + a1) + (a2 + a3);
}

__device__ __forceinline__ float matvec(const float* __restrict__ v,
                                        const float* __restrict__ Wt,
                                        int d, int stride, int K) {
    float a0 = 0.f, a1 = 0.f, a2 = 0.f, a3 = 0.f;
#pragma unroll 8
    for (int k = 0; k < K; k += 4) {
        a0 = fmaf(v[k],     Wt[(k)     * stride + d], a0);
        a1 = fmaf(v[k + 1], Wt[(k + 1) * stride + d], a1);
        a2 = fmaf(v[k + 2], Wt[(k + 2) * stride + d], a2);
        a3 = fmaf(v[k + 3], Wt[(k + 3) * stride + d], a3);
    }
    return (a0 + a1) + (a2 + a3);
}

// ---------------- 8-row k-split GEMM stage (smem weights) -------------------
// gsel: 0 linear, 1 Llist, 2 tgtL, 3 relu(rowSlot? aggAux : in)
struct GJob {
    const float* in; const float* pA; const float* bias;
    float* out;
    int gsel, woff, cnt;
};

__device__ void gemm_part(float* sm, GJob jb, int b0, int b1) {
    int bid = blockIdx.x;
    if (bid < b0 || bid >= b1) return;
    float* s_w = sm;                                        // 16384 floats
    float (*s_in)[HH] = (float(*)[HH])(sm + 16384);         // 8 x 128
    float4 (*s_part)[8][32] = (float4(*)[8][32])(sm + 16384 + 8 * HH);
    int tid = threadIdx.x, w = tid >> 5, lane = tid & 31;
    int k4 = lane * 4;
    int cnt = jb.cnt;
    int T = (cnt + 7) >> 3;
    int stride = b1 - b0;
    const float4* wp = (const float4*)(g_Wt + jb.woff);
    bool loaded = false;

    for (int t = bid - b0; t < T; t += stride) {
        if (!loaded) {
            for (int i = tid; i < 4096; i += NTHR)
                ((float4*)s_w)[i] = wp[i];
            loaded = true;
        }
        int r0 = t * 8;
        {
            int r = r0 + w;
            int rc = (r < cnt) ? r : (cnt - 1);
            float4 v;
            if (jb.gsel == 0) {
                v = *(const float4*)(jb.in + (size_t)rc * HH + k4);
            } else if (jb.gsel == 1) {
                v = *(const float4*)(jb.in + (size_t)g_Llist[rc] * HH + k4);
            } else if (jb.gsel == 2) {
                v = *(const float4*)(jb.in + (size_t)g_tgtL[rc] * HH + k4);
            } else {
                int s = g_rowSlot[rc];
                const float* src = (s > 0) ? (jb.pA + (size_t)(s - 1) * HH)
                                           : (jb.in + (size_t)rc * HH);
                v = relu4(*(const float4*)(src + k4));
            }
            *(float4*)(&s_in[w][k4]) = v;
        }
        __syncthreads();

        float4 acc[8];
#pragma unroll
        for (int r = 0; r < 8; r++) acc[r] = make_float4(0.f, 0.f, 0.f, 0.f);
        int kbase = w * 16;
#pragma unroll
        for (int kk = 0; kk < 16; kk++) {
            int k = kbase + kk;
            float4 wv = ((const float4*)s_w)[k * 32 + lane];
#pragma unroll
            for (int r = 0; r < 8; r++) {
                float xv = s_in[r][k];
                acc[r].x = fmaf(xv, wv.x, acc[r].x);
                acc[r].y = fmaf(xv, wv.y, acc[r].y);
                acc[r].z = fmaf(xv, wv.z, acc[r].z);
                acc[r].w = fmaf(xv, wv.w, acc[r].w);
            }
        }
#pragma unroll
        for (int r = 0; r < 8; r++) s_part[w][r][lane] = acc[r];
        __syncthreads();

        {
            float4 o = s_part[0][w][lane];
#pragma unroll
            for (int ww = 1; ww < 8; ww++) {
                float4 p = s_part[ww][w][lane];
                o.x += p.x; o.y += p.y; o.z += p.z; o.w += p.w;
            }
            float4 bv = jb.bias ? ((const float4*)jb.bias)[lane]
                                : make_float4(0.f, 0.f, 0.f, 0.f);
            int row = r0 + w;
            if (row < cnt) {
                o.x += bv.x; o.y += bv.y; o.z += bv.z; o.w += bv.w;
                *(float4*)(jb.out + (size_t)row * HH + k4) = o;
            }
        }
        __syncthreads();
    }
}

// ---------------- fin: per-slot attention finish (no pair GEMMs) ------------
__device__ void fin_stage(float* sm,
                          const float* __restrict__ Mk, const float* __restrict__ Mv,
                          const float* __restrict__ bvp,
                          const float* __restrict__ Wc, const float* __restrict__ cb,
                          const float* __restrict__ Wop, const float* __restrict__ opB,
                          const float* __restrict__ W1, const float* __restrict__ b1) {
    float (*sP)[4] = (float(*)[4])sm;              // 512*4
    float* sT   = sm + 2048;                       // 512
    int*   sNbr = (int*)(sm + 2560);               // 512
    float* sQ   = sm + 3072;                       // 128
    float (*sQK)[128] = (float(*)[128])(sm + 3200);// 4*128
    float (*sAh)[128] = (float(*)[128])(sm + 3712);// 4*128
    float* sAvv = sm + 4224;                       // 128
    float* sTgt = sm + 4352;                       // 128
    float* sOut = sm + 4480;                       // 128
    float (*sPart)[128] = (float(*)[128])(sm + 4608); // 2*128
    int tid = threadIdx.x, w = tid >> 5, lane = tid & 31;
    int half = tid >> 7, dd = tid & 127;

    for (int u = blockIdx.x; u < UCNT; u += gridDim.x) {
        int off = g_poff[u];
        int dg = g_poff[u + 1] - off;
        for (int j = tid; j < dg; j += NTHR) {
            sT[j] = g_pT[off + j];
            sNbr[j] = g_pNbrRow[off + j];
        }
        if (tid < 128) {
            sQ[dd] = g_q[(size_t)u * HH + dd];
            sTgt[dd] = g_tfL[(size_t)g_tgtL[u] * HH + dd];
        }
        __syncthreads();

        // QK[h][j2] = sum_{d2<32} q[h*32+d2] * Mk[j2*128 + h*32 + d2]
        if (dg > 0) {
#pragma unroll
            for (int pass = 0; pass < 2; pass++) {
                int idx = pass * NTHR + tid;
                int h = idx >> 7, j2 = idx & 127;
                const float* mrow = Mk + j2 * HH + h * 32;
                const float* qrow = sQ + h * 32;
                float acc = 0.f;
#pragma unroll 8
                for (int d2 = 0; d2 < 32; d2++)
                    acc = fmaf(qrow[d2], mrow[d2], acc);
                sQK[h][j2] = acc;
            }
        }
        __syncthreads();

        // scores: warp per edge
        {
            int k4 = lane * 4;
            float4 q4 = *(const float4*)(sQ + k4);
            float4 w1v = *(const float4*)(W1 + k4);
            float4 b1v = *(const float4*)(b1 + k4);
            int myh = lane >> 3;
            for (int j = w; j < dg; j += 8) {
                float t = sT[j];
                float4 hv;
                hv.x = fmaxf(fmaf(t, w1v.x, b1v.x), 0.f);
                hv.y = fmaxf(fmaf(t, w1v.y, b1v.y), 0.f);
                hv.z = fmaxf(fmaf(t, w1v.z, b1v.z), 0.f);
                hv.w = fmaxf(fmaf(t, w1v.w, b1v.w), 0.f);
                float4 av = *(const float4*)(g_Ak + (size_t)sNbr[j] * HH + k4);
                float nd = q4.x * av.x + q4.y * av.y + q4.z * av.z + q4.w * av.w;
                float p0 = sQK[0][k4] * hv.x + sQK[0][k4+1] * hv.y
                         + sQK[0][k4+2] * hv.z + sQK[0][k4+3] * hv.w;
                float p1 = sQK[1][k4] * hv.x + sQK[1][k4+1] * hv.y
                         + sQK[1][k4+2] * hv.z + sQK[1][k4+3] * hv.w;
                float p2 = sQK[2][k4] * hv.x + sQK[2][k4+1] * hv.y
                         + sQK[2][k4+2] * hv.z + sQK[2][k4+3] * hv.w;
                float p3 = sQK[3][k4] * hv.x + sQK[3][k4+1] * hv.y
                         + sQK[3][k4+2] * hv.z + sQK[3][k4+3] * hv.w;
                if (myh == 0) p0 += nd;
                else if (myh == 1) p1 += nd;
                else if (myh == 2) p2 += nd;
                else p3 += nd;
#pragma unroll
                for (int m = 16; m > 0; m >>= 1) {
                    p0 += __shfl_xor_sync(0xffffffffu, p0, m);
                    p1 += __shfl_xor_sync(0xffffffffu, p1, m);
                    p2 += __shfl_xor_sync(0xffffffffu, p2, m);
                    p3 += __shfl_xor_sync(0xffffffffu, p3, m);
                }
                if (lane == 0) {
                    sP[j][0] = p0 * DSCALE; sP[j][1] = p1 * DSCALE;
                    sP[j][2] = p2 * DSCALE; sP[j][3] = p3 * DSCALE;
                }
            }
        }
        __syncthreads();

        // softmax per head (warps 0-3)
        if (tid < 128) {
            int ln = tid & 31, hh = tid >> 5;
            float mx = -1e30f;
            for (int j = ln; j < dg; j += 32) mx = fmaxf(mx, sP[j][hh]);
#pragma unroll
            for (int m = 16; m > 0; m >>= 1)
                mx = fmaxf(mx, __shfl_xor_sync(0xffffffffu, mx, m));
            float smv = 0.f;
            for (int j = ln; j < dg; j += 32) {
                float p = expf(sP[j][hh] - mx);
                sP[j][hh] = p;
                smv += p;
            }
#pragma unroll
            for (int m = 16; m > 0; m >>= 1)
                smv += __shfl_xor_sync(0xffffffffu, smv, m);
            float inv = (dg > 0) ? (1.f / smv) : 0.f;
            for (int j = ln; j < dg; j += 32) sP[j][hh] *= inv;
        }
        __syncthreads();

        // ah[h][j2] = sum_j p[j][h] * relu(t_j*W1[j2]+b1[j2])  (ascending j)
#pragma unroll
        for (int pass = 0; pass < 2; pass++) {
            int idx = pass * NTHR + tid;
            int h = idx >> 7, j2 = idx & 127;
            float w1s = W1[j2], b1s = b1[j2];
            float acc = 0.f;
            for (int j = 0; j < dg; j++) {
                float hv = fmaxf(fmaf(sT[j], w1s, b1s), 0.f);
                acc = fmaf(sP[j][h], hv, acc);
            }
            sAh[h][j2] = acc;
        }
        // weighted Av sum (ascending j, deterministic)
        if (tid < 128) {
            int h = dd >> 5;
            float acc = 0.f;
            for (int j = 0; j < dg; j++)
                acc = fmaf(sP[j][h], g_Av[(size_t)sNbr[j] * HH + dd], acc);
            sAvv[dd] = acc;
        }
        __syncthreads();

        // Mv matvec on per-head ah (halved over 256 threads)
        {
            int h = dd >> 5;
            const float* base = Mv + (size_t)half * 64 * HH + dd;
            const float* ah = sAh[h] + half * 64;
            float a0 = 0.f, a1 = 0.f;
#pragma unroll 8
            for (int j2 = 0; j2 < 64; j2 += 2) {
                a0 = fmaf(ah[j2],     base[(size_t)j2 * HH], a0);
                a1 = fmaf(ah[j2 + 1], base[(size_t)(j2 + 1) * HH], a1);
            }
            sPart[half][dd] = a0 + a1;
        }
        __syncthreads();
        if (tid < 128)
            sOut[dd] = sAvv[dd] + sPart[0][dd] + sPart[1][dd] + bvp[dd];
        __syncthreads();

        // combined (Wop@Wao) matvec OR Wop on tf[tgt]
        {
            const float* src = (dg > 0) ? sOut : sTgt;
            const float* W = (dg > 0) ? Wc : Wop;
            sPart[half][dd] = matvec64(src + half * 64, W + (size_t)half * 64 * HH, dd, HH);
        }
        __syncthreads();
        if (tid < 128) {
            const float* bb = (dg > 0) ? cb : opB;
            g_agg[(size_t)u * HH + dd] = sPart[0][dd] + sPart[1][dd] + bb[dd];
        }
        __syncthreads();
    }
}

// ---------------- mega kernel ----------------
struct Params {
    const float* wsrc[19];
    const int *tp, *src, *dst;
    const float *ets, *nf;
    const float *in_b, *teW1, *teB1, *teB2, *aiB, *aoB, *ftB, *opB;
    const float *o1B, *o2B, *l1B, *l2B, *l3W, *l3B;
};

__global__ void __launch_bounds__(NTHR)
k_mega(Params P, float* out) {
    extern __shared__ float sm[];
    const int gt = blockIdx.x * NTHR + threadIdx.x;
    const int gs = gridDim.x * NTHR;
    int tid = threadIdx.x;
    int nb = gridDim.x;

    // ---- S0: weight transpose + mark targets ----
    for (int m = 0; m < 19; m++) {
        int outD = c_moutD[m];
        int tot = outD * 128;
        const float* s = P.wsrc[m];
        float* dst = g_Wt + c_moff[m];
        for (int i = gt; i < tot; i += gs) {
            int j = i >> 7, k = i & 127;
            dst[k * outD + j] = s[i];
        }
    }
    if (gt < UCNT) {
        int t = P.tp[gt];
        atomicMax(&g_n2s[t], gt + 1);
        g_nneed[t] = 1;
    }
    gridsync();

    // ---- S1: edge scan ----
    for (int i = gt; i < NE; i += gs) {
        int s = P.src[i], d = P.dst[i];
        int su = g_n2s[s] - 1;
        if (su >= 0) {
            int j = atomicAdd(&g_deg[su], 1);
            if (j < MAXDEG) { g_eidx[su * MAXDEG + j] = i; g_nbr[su * MAXDEG + j] = d; }
            g_nneed[d] = 1;
        }
        int du = g_n2s[d] - 1;
        if (du >= 0 && d != s) {
            int j = atomicAdd(&g_deg[du], 1);
            if (j < MAXDEG) { g_eidx[du * MAXDEG + j] = i; g_nbr[du * MAXDEG + j] = s; }
            g_nneed[s] = 1;
        }
    }
    gridsync();

    // ---- S2: node compaction + deg clamp + pair prefix scan (block 0) ----
    for (int i = gt; i < NN; i += gs)
        if (g_nneed[i]) { int p = atomicAdd(&g_Lcnt, 1); g_Llist[p] = i; g_nodeL[i] = p; }
    if (blockIdx.x == 0) {
        if (tid < UCNT) {
            int dd = g_deg[tid];
            if (dd > MAXDEG) g_deg[tid] = MAXDEG;
        }
        __syncthreads();
        __shared__ int sCnt[UCNT];
        if (tid < UCNT) {
            int c = g_n2s[P.tp[tid]] - 1;
            sCnt[tid] = g_deg[c];
        }
        __syncthreads();
        if (tid == 0) {
            int acc = 0;
            for (int i = 0; i < UCNT; i++) {
                g_poff[i] = acc;
                acc += sCnt[i];
            }
            g_poff[UCNT] = acc;
            g_Ptot = acc;
        }
    }
    gridsync();

    // ---- S3: sort + finalize + pSlot fill + x GEMM + 6 combines + biases ----
    for (int u = blockIdx.x; u < UCNT; u += gridDim.x) {
        int* se = (int*)sm;
        int* sn = se + MAXDEG;
        int dg = g_deg[u];
        for (int j = tid; j < dg; j += NTHR) {
            se[j] = g_eidx[u * MAXDEG + j];
            sn[j] = g_nbr[u * MAXDEG + j];
        }
        __syncthreads();
        if (tid == 0) {
            for (int i = 1; i < dg; i++) {
                int ke = se[i], kn = sn[i], j = i - 1;
                while (j >= 0 && se[j] > ke) { se[j+1] = se[j]; sn[j+1] = sn[j]; j--; }
                se[j+1] = ke; sn[j+1] = kn;
            }
            int t = P.tp[u];
            g_tgtL[u] = g_nodeL[t];
            int c = g_n2s[t];
            g_canon[u] = c;
            if (c - 1 == u) g_rowSlot[g_nodeL[t]] = u + 1;
        }
        __syncthreads();
        for (int j = tid; j < dg; j += NTHR) {
            g_eidx[u * MAXDEG + j] = se[j];
            g_nbr[u * MAXDEG + j] = sn[j];
        }
        int off = g_poff[u], cntp = g_poff[u + 1] - off;
        for (int j = tid; j < cntp; j += NTHR) g_pSlot[off + j] = u;
        __syncthreads();
    }
    // biases (runs in low blocks; independent of GEMM below)
    if (gt < 256) {          // bvp[l][d] = sum_k b2[k]*Wvt[k*128+d] + bv[d]
        int l = gt >> 7, d = gt & 127;
        const float* Wvt = g_Wt + c_moff[5 + 7 * l];
        const float* b2 = P.teB2 + l * 128;
        float a = P.aiB[l * 384 + 256 + d];
        for (int k = 0; k < 128; k++) a = fmaf(b2[k], Wvt[k * 128 + d], a);
        g_bvp[gt] = a;
    } else if (gt < 512) {   // cb = Wop@aoB + opB
        int i = gt - 256;
        int l = i >> 7, d = i & 127;
        const float* Wopt = g_Wt + c_moff[7 + 7 * l];
        const float* aoB = P.aoB + l * 128;
        float a = P.opB[l * 128 + d];
        for (int k = 0; k < 128; k++) a = fmaf(aoB[k], Wopt[k * 128 + d], a);
        g_cb[i] = a;
    }
    {
        int xb = nb - 48;
        GJob jx = { P.nf, 0, P.in_b, g_xL, 1, c_moff[0], g_Lcnt };
        gemm_part(sm, jx, 0, xb);
        // combines: rows = transposed source (te2t or Wao_t), weights = Wk/Wv/Wop
        GJob c0 = { g_Wt + c_moff[2],  0, nullptr, g_Wt + MK0, 0, c_moff[4],  128 };
        gemm_part(sm, c0, xb,      xb + 8);
        GJob c1 = { g_Wt + c_moff[2],  0, nullptr, g_Wt + MV0, 0, c_moff[5],  128 };
        gemm_part(sm, c1, xb + 8,  xb + 16);
        GJob c2 = { g_Wt + c_moff[9],  0, nullptr, g_Wt + MK1, 0, c_moff[11], 128 };
        gemm_part(sm, c2, xb + 16, xb + 24);
        GJob c3 = { g_Wt + c_moff[9],  0, nullptr, g_Wt + MV1, 0, c_moff[12], 128 };
        gemm_part(sm, c3, xb + 24, xb + 32);
        GJob c4 = { g_Wt + c_moff[6],  0, nullptr, g_Wt + CW0, 0, c_moff[7],  128 };
        gemm_part(sm, c4, xb + 32, xb + 40);
        GJob c5 = { g_Wt + c_moff[13], 0, nullptr, g_Wt + CW1, 0, c_moff[14], 128 };
        gemm_part(sm, c5, xb + 40, xb + 48);
    }
    gridsync();

    // ---- S4: pair metadata fill + tf0 ----
    {
        int Pt = g_Ptot;
        for (int p = gt; p < Pt; p += gs) {
            int u = g_pSlot[p];
            int cu = g_canon[u] - 1;
            int j = p - g_poff[u];
            g_pT[p] = P.ets[g_eidx[cu * MAXDEG + j]];
            g_pNbrRow[p] = g_nodeL[g_nbr[cu * MAXDEG + j]];
        }
        GJob j = { g_xL, 0, P.ftB, g_tfL, 0, c_moff[1], g_Lcnt };
        gemm_part(sm, j, 0, nb);
    }
    gridsync();

    for (int l = 0; l < 2; l++) {
        int base = l * 7;
        const float* bq = P.aiB + l * 384;
        // ---- Ak / Av / q (block-partitioned) ----
        {
            GJob ja = { g_tfL, 0, nullptr, g_Ak, 0, c_moff[4 + base], g_Lcnt };
            gemm_part(sm, ja, 0, 64);
            GJob jv = { g_tfL, 0, nullptr, g_Av, 0, c_moff[5 + base], g_Lcnt };
            gemm_part(sm, jv, 64, 128);
            GJob jq = { g_tfL, 0, bq, g_q, 2, c_moff[3 + base], UCNT };
            gemm_part(sm, jq, 128, nb);
        }
        gridsync();
        // ---- fin ----
        fin_stage(sm,
                  g_Wt + (l == 0 ? MK0 : MK1), g_Wt + (l == 0 ? MV0 : MV1),
                  g_bvp + l * HH,
                  g_Wt + (l == 0 ? CW0 : CW1), g_cb + l * HH,
                  g_Wt + c_moff[7 + base], P.opB + l * HH,
                  P.teW1 + l * 128, P.teB1 + l * 128);
        gridsync();
        // ---- tf1 ----
        if (l == 0) {
            GJob j = { g_xL, g_agg, P.ftB + 128, g_tfL, 3, c_moff[8], g_Lcnt };
            gemm_part(sm, j, 0, nb);
            gridsync();
        }
    }

    // ---- tail: fused out1/out2/lp1/lp2/lp3 per pair ----
    {
        float (*sAgg)[HH] = (float(*)[HH])sm;
        float (*sE1)[HH]  = (float(*)[HH])(sm + 256);
        float (*sEmb)[64] = (float(*)[64])(sm + 512);
        float* sZ1 = sm + 640;
        float* sZ2 = sm + 768;
        float* sRed = sm + 832;
        int nn = tid >> 7, dd = tid & 127;
        const float* o1Wt = g_Wt + c_moff[15];
        const float* o2Wt = g_Wt + c_moff[16];
        const float* l1Wt = g_Wt + c_moff[17];
        const float* l2Wt = g_Wt + c_moff[18];

        for (int p = blockIdx.x; p < 128; p += gridDim.x) {
            sAgg[nn][dd] = fmaxf(g_agg[(size_t)(2 * p + nn) * HH + dd], 0.f);
            __syncthreads();
            sE1[nn][dd] = fmaxf(matvec(sAgg[nn], o1Wt, dd, HH, HH) + P.o1B[dd], 0.f);
            __syncthreads();
            if (dd < 64)
                sEmb[nn][dd] = matvec(sE1[nn], o2Wt, dd, 64, HH) + P.o2B[dd];
            __syncthreads();
            if (tid < 128) {
                float a0 = 0.f, a1 = 0.f;
#pragma unroll 8
                for (int k = 0; k < 64; k += 2) {
                    a0 = fmaf(sEmb[0][k],     l1Wt[(k)      * HH + dd], a0);
                    a1 = fmaf(sEmb[0][k + 1], l1Wt[(k + 1)  * HH + dd], a1);
                }
#pragma unroll 8
                for (int k = 0; k < 64; k += 2) {
                    a0 = fmaf(sEmb[1][k],     l1Wt[(64 + k)     * HH + dd], a0);
                    a1 = fmaf(sEmb[1][k + 1], l1Wt[(64 + k + 1) * HH + dd], a1);
                }
                sZ1[dd] = fmaxf(a0 + a1 + P.l1B[dd], 0.f);
            }
            __syncthreads();
            if (tid < 64)
                sZ2[tid] = fmaxf(matvec(sZ1, l2Wt, tid, 64, HH) + P.l2B[tid], 0.f);
            __syncthreads();
            if (tid < 64) {
                float part = sZ2[tid] * P.l3W[tid];
                part += __shfl_xor_sync(0xffffffffu, part, 16);
                part += __shfl_xor_sync(0xffffffffu, part, 8);
                part += __shfl_xor_sync(0xffffffffu, part, 4);
                part += __shfl_xor_sync(0xffffffffu, part, 2);
                part += __shfl_xor_sync(0xffffffffu, part, 1);
                if ((tid & 31) == 0) sRed[tid >> 5] = part;
            }
            __syncthreads();
            if (tid == 0)
                out[p] = 1.f / (1.f + expf(-(sRed[0] + sRed[1] + P.l3B[0])));
            __syncthreads();
        }
    }

    // ---- cleanup for next graph replay ----
    for (int i = gt; i < NN; i += gs) g_nneed[i] = 0;
    if (gt < UCNT) {
        g_n2s[P.tp[gt]] = 0;
        g_deg[gt] = 0;
        g_rowSlot[g_tgtL[gt]] = 0;
    }
    if (gt == 0) g_Lcnt = 0;
}

// ---------------- launch ----------------
extern "C" void kernel_launch(void* const* d_in, const int* in_sizes, int n_in,
                              void* d_out, int out_size) {
    const float* nf   = (const float*)d_in[0];
    const int*   eidx = (const int*)d_in[1];
    const float* ets  = (const float*)d_in[2];
    const int*   tp   = (const int*)d_in[3];
    const float* in_W = (const float*)d_in[4];
    const float* in_b = (const float*)d_in[5];
    const float* teW1 = (const float*)d_in[6];
    const float* teB1 = (const float*)d_in[7];
    const float* teW2 = (const float*)d_in[8];
    const float* teB2 = (const float*)d_in[9];
    const float* aiW  = (const float*)d_in[10];
    const float* aiB  = (const float*)d_in[11];
    const float* aoW  = (const float*)d_in[12];
    const float* aoB  = (const float*)d_in[13];
    const float* ftW  = (const float*)d_in[14];
    const float* ftB  = (const float*)d_in[15];
    const float* opW  = (const float*)d_in[16];
    const float* opB  = (const float*)d_in[17];
    const float* o1W  = (const float*)d_in[18];
    const float* o1B  = (const float*)d_in[19];
    const float* o2W  = (const float*)d_in[20];
    const float* o2B  = (const float*)d_in[21];
    const float* l1W  = (const float*)d_in[22];
    const float* l1B  = (const float*)d_in[23];
    const float* l2W  = (const float*)d_in[24];
    const float* l2B  = (const float*)d_in[25];
    const float* l3W  = (const float*)d_in[26];
    const float* l3B  = (const float*)d_in[27];
    float* out = (float*)d_out;

    Params P;
    P.wsrc[0] = in_W;
    for (int l = 0; l < 2; l++) {
        P.wsrc[1 + 7*l] = ftW + l * 16384;
        P.wsrc[2 + 7*l] = teW2 + l * 16384;
        P.wsrc[3 + 7*l] = aiW + l * 384 * 128;            // Wq
        P.wsrc[4 + 7*l] = aiW + l * 384 * 128 + 16384;    // Wk
        P.wsrc[5 + 7*l] = aiW + l * 384 * 128 + 32768;    // Wv
        P.wsrc[6 + 7*l] = aoW + l * 16384;
        P.wsrc[7 + 7*l] = opW + l * 16384;
    }
    P.wsrc[15] = o1W; P.wsrc[16] = o2W; P.wsrc[17] = l1W; P.wsrc[18] = l2W;
    P.tp = tp; P.src = eidx; P.dst = eidx + NE;
    P.ets = ets; P.nf = nf;
    P.in_b = in_b; P.teW1 = teW1; P.teB1 = teB1; P.teB2 = teB2;
    P.aiB = aiB; P.aoB = aoB; P.ftB = ftB; P.opB = opB;
    P.o1B = o1B; P.o2B = o2B; P.l1B = l1B; P.l2B = l2B;
    P.l3W = l3W; P.l3B = l3B;

    cudaFuncSetAttribute(k_mega, cudaFuncAttributeMaxDynamicSharedMemorySize, SMEM_SZ);

    int nSM = 148;
    cudaDeviceGetAttribute(&nSM, cudaDevAttrMultiProcessorCount, 0);
    int nb = nSM;              // 1 block per SM
    if (nb < 136) nb = 136;    // partitions require nb > 128

    k_mega<<<nb, NTHR, SMEM_SZ>>>(P, out);
}